// round 1
// baseline (speedup 1.0000x reference)
#include <cuda_runtime.h>

// Problem constants (fixed by reference setup_inputs)
#define BB 128
#define SS 256
#define HH 768
#define KK 64
#define NROWS (BB * SS)     // 32768
#define V4_PER_ROW (HH / 4) // 192

// Per-row multipliers, computed by kernel 1, consumed by kernel 2.
// 3 * 32768 * 4B = 384 KB -> L2 resident.
__device__ float g_m_dep[NROWS];
__device__ float g_m_dpd[NROWS];
__device__ float g_m_mul[NROWS];

// Kernel 1: grid = B blocks, 256 threads (one per position s).
__global__ void compute_mults_kernel(const int* __restrict__ depend,
                                     const int* __restrict__ depended,
                                     const int* __restrict__ noconn,
                                     const float* __restrict__ dep_w,
                                     const float* __restrict__ dpd_w) {
    const int b = blockIdx.x;
    const int s = threadIdx.x;

    __shared__ int sh[3 * KK];
    if (s < KK)            sh[s]            = depend  [b * KK + s];
    else if (s < 2 * KK)   sh[s]            = depended[b * KK + (s - KK)];
    else if (s < 3 * KK)   sh[s]            = noconn  [b * KK + (s - 2 * KK)];
    __syncthreads();

    const int target = s - 1;  // s=0 -> target=-1, never matches (idx >= 0)
    bool dep = false, dpd = false, noc = false;
#pragma unroll
    for (int k = 0; k < KK; k++) {
        dep |= (sh[k]          == target);
        dpd |= (sh[KK + k]     == target);
        noc |= (sh[2 * KK + k] == target);
    }
    // Note: idx values are in [0, S); since target <= S-2, idx == S-1 never
    // matches, which exactly reproduces the reference's (idx+1 < S) validity.

    const float w1 = dep_w[b];
    const float w2 = dpd_w[b];

    float m_dep = (s == 0 || dep) ? 1.0f : 0.0f;
    float m_dpd = (s == 0 || dpd) ? 1.0f : 0.0f;
    float m     = dep ? w1 : 0.0f;
    if (dpd)    m = w2;
    if (noc)    m = 0.0f;
    if (s == 0) m = 1.0f;

    const int row = b * SS + s;
    g_m_dep[row] = m_dep;
    g_m_dpd[row] = m_dpd;
    g_m_mul[row] = m;
}

// Kernel 2: one block per (b,s) row; 192 threads, one float4 each.
// Fully coalesced 3072B reads and 3x 3072B writes per block.
__global__ __launch_bounds__(V4_PER_ROW) void apply_kernel(
    const float4* __restrict__ in, float4* __restrict__ out) {
    const int row = blockIdx.x;
    const int t   = threadIdx.x;

    const float m0 = g_m_dep[row];
    const float m1 = g_m_dpd[row];
    const float m2 = g_m_mul[row];

    const long idx = (long)row * V4_PER_ROW + t;
    const float4 v = in[idx];

    float4 a, b, c;
    a.x = v.x * m0; a.y = v.y * m0; a.z = v.z * m0; a.w = v.w * m0;
    b.x = v.x * m1; b.y = v.y * m1; b.z = v.z * m1; b.w = v.w * m1;
    c.x = v.x * m2; c.y = v.y * m2; c.z = v.z * m2; c.w = v.w * m2;

    const long N4 = (long)NROWS * V4_PER_ROW;
    out[idx]          = a;
    out[N4 + idx]     = b;
    out[2 * N4 + idx] = c;
}

extern "C" void kernel_launch(void* const* d_in, const int* in_sizes, int n_in,
                              void* d_out, int out_size) {
    const float* bert     = (const float*)d_in[0];
    const int*   depend   = (const int*)d_in[1];
    const int*   depended = (const int*)d_in[2];
    const int*   noconn   = (const int*)d_in[3];
    const float* dep_w    = (const float*)d_in[4];
    const float* dpd_w    = (const float*)d_in[5];
    float*       out      = (float*)d_out;

    compute_mults_kernel<<<BB, SS>>>(depend, depended, noconn, dep_w, dpd_w);
    apply_kernel<<<NROWS, V4_PER_ROW>>>((const float4*)bert, (float4*)out);
}

// round 3
// speedup vs baseline: 1.0318x; 1.0318x over previous
#include <cuda_runtime.h>

// Problem constants (fixed by reference setup_inputs)
#define BB 128
#define SS 256
#define HH 768
#define KK 64
#define NROWS (BB * SS)     // 32768
#define V4_PER_ROW (HH / 4) // 192

// Fused kernel: one block per (b,s) row, 192 threads, one float4 each.
//
// Membership: thread t<64 checks depend[k=t], t in [64,128) depended,
// t in [128,192) no_connect, each against target = s-1. Hits are bit-packed
// (1=dep, 2=dpd, 4=noc) and OR-combined via a shared word + atomicOr_block
// (NOT __syncthreads_or, which is a predicate-any, not a bitwise OR).
// Index arrays are 96 KB total -> L2-resident; the membership loads and two
// barriers are hidden under the block's 12 KB of streaming HBM traffic.
//
// Validity: indices lie in [0, S) and target <= S-2, so idx == S-1 never
// matches -- exactly reproducing the reference's (idx + 1 < S) check.
__global__ __launch_bounds__(V4_PER_ROW) void fused_kernel(
    const float4* __restrict__ in,
    const int*    __restrict__ depend,
    const int*    __restrict__ depended,
    const int*    __restrict__ noconn,
    const float*  __restrict__ dep_w,
    const float*  __restrict__ dpd_w,
    float4*       __restrict__ out)
{
    const int row = blockIdx.x;
    const int b   = row >> 8;     // row / SS
    const int s   = row & (SS-1); // row % SS
    const int t   = threadIdx.x;
    const int target = s - 1;     // s=0 -> -1, never matches (idx >= 0)

    __shared__ int sh_hits;
    if (t == 0) sh_hits = 0;

    int flag;
    if (t < KK) {
        flag = (__ldg(&depend[b * KK + t]) == target) ? 1 : 0;
    } else if (t < 2 * KK) {
        flag = (__ldg(&depended[b * KK + (t - KK)]) == target) ? 2 : 0;
    } else {
        flag = (__ldg(&noconn[b * KK + (t - 2 * KK)]) == target) ? 4 : 0;
    }

    __syncthreads();                 // sh_hits = 0 visible
    if (flag) atomicOr_block(&sh_hits, flag);
    __syncthreads();                 // all hits accumulated
    const int hits = sh_hits;

    const bool dep = (hits & 1) != 0;
    const bool dpd = (hits & 2) != 0;
    const bool noc = (hits & 4) != 0;
    const bool p0  = (s == 0);

    const float m0 = (p0 || dep) ? 1.0f : 0.0f;
    const float m1 = (p0 || dpd) ? 1.0f : 0.0f;
    float m2 = dep ? __ldg(&dep_w[b]) : 0.0f;
    if (dpd) m2 = __ldg(&dpd_w[b]);
    if (noc) m2 = 0.0f;
    if (p0)  m2 = 1.0f;

    const long idx = (long)row * V4_PER_ROW + t;
    const float4 v = __ldcs(&in[idx]);   // read-once: evict-first

    float4 a, bb, c;
    a.x  = v.x * m0; a.y  = v.y * m0; a.z  = v.z * m0; a.w  = v.w * m0;
    bb.x = v.x * m1; bb.y = v.y * m1; bb.z = v.z * m1; bb.w = v.w * m1;
    c.x  = v.x * m2; c.y  = v.y * m2; c.z  = v.z * m2; c.w  = v.w * m2;

    const long N4 = (long)NROWS * V4_PER_ROW;
    __stcs(&out[idx],          a);       // write-once: evict-first
    __stcs(&out[N4 + idx],     bb);
    __stcs(&out[2 * N4 + idx], c);
}

extern "C" void kernel_launch(void* const* d_in, const int* in_sizes, int n_in,
                              void* d_out, int out_size) {
    const float* bert     = (const float*)d_in[0];
    const int*   depend   = (const int*)d_in[1];
    const int*   depended = (const int*)d_in[2];
    const int*   noconn   = (const int*)d_in[3];
    const float* dep_w    = (const float*)d_in[4];
    const float* dpd_w    = (const float*)d_in[5];
    float*       out      = (float*)d_out;

    fused_kernel<<<NROWS, V4_PER_ROW>>>((const float4*)bert, depend, depended,
                                        noconn, dep_w, dpd_w, (float4*)out);
}